// round 8
// baseline (speedup 1.0000x reference)
#include <cuda_runtime.h>
#include <cuda_fp16.h>
#include <math.h>
#include <stdint.h>

// ---------------- problem constants ----------------
#define BATCH     32768
#define DIM       128
#define NCENT     6400
#define KC        64
#define AMT       (BATCH / 16)     // 2048 A row-tiles (m16)
#define BNT       (NCENT / 8)      // 800  B col-tiles (n8)
#define NSLICES   8
#define NSLC_T    100              // n8-tiles per N-slice (800 centers)
#define NUNITS    (512 * NSLICES)  // 4096 units
#define GRID_SW   592              // 148 SMs x occ 4

// ---------------- device scratch ----------------
__device__ uint4 g_afrag[AMT][8][32];      // 8.4 MB  (fp16 a-plane, A frag layout)
__device__ uint2 g_bfrag[BNT][8][32];      // 1.6 MB  (fp16 a-plane, B frag layout)
__device__ float g_c2[NCENT];
__device__ float g_x2[BATCH];
__device__ float g_xb2[BATCH];             // || x - fp16(x) ||^2 per row
__device__ unsigned int g_best1[BATCH];    // enc(approx sq)
__device__ unsigned long long g_best2[BATCH]; // enc(exact sq)<<32 | idx
__device__ int g_t1, g_t2;
__device__ unsigned int g_mc2e, g_mcb2e;   // enc(max ||c||^2), enc(max ||c_b||^2)

// ---------------- helpers ----------------
__device__ __forceinline__ uint32_t packh(float lo, float hi) {
    __half2 h = __floats2half2_rn(lo, hi);
    return *reinterpret_cast<uint32_t*>(&h);
}
__device__ __forceinline__ float h16(float v) {
    return __half2float(__float2half_rn(v));
}
__device__ __forceinline__ uint32_t encf(float f) {
    uint32_t u = __float_as_uint(f);
    return (u & 0x80000000u) ? ~u : (u | 0x80000000u);
}
__device__ __forceinline__ float decf(uint32_t e) {
    uint32_t u = (e & 0x80000000u) ? (e ^ 0x80000000u) : ~e;
    return __uint_as_float(u);
}
__device__ __forceinline__ void mma16816(float* d, const uint4& a,
                                         uint32_t b0, uint32_t b1) {
    asm volatile(
        "mma.sync.aligned.m16n8k16.row.col.f32.f16.f16.f32 "
        "{%0,%1,%2,%3}, {%4,%5,%6,%7}, {%8,%9}, {%0,%1,%2,%3};"
        : "+f"(d[0]), "+f"(d[1]), "+f"(d[2]), "+f"(d[3])
        : "r"(a.x), "r"(a.y), "r"(a.z), "r"(a.w), "r"(b0), "r"(b1));
}

// ---------------------------------------------------------------------------
// prep A: one warp per x row -> x2, xb2, a-plane A fragment, global resets
// ---------------------------------------------------------------------------
__global__ void prep_ax_kernel(const float* __restrict__ x) {
    int warp = (blockIdx.x * blockDim.x + threadIdx.x) >> 5;
    int lane = threadIdx.x & 31;
    if (warp >= BATCH) return;
    int r = warp;
    int M = r >> 4, g = r & 15;
    int kt = lane >> 2, t = lane & 3;
    const float* row = x + (size_t)r * DIM;
    float2 lo = *reinterpret_cast<const float2*>(row + kt * 16 + 2 * t);
    float2 hi = *reinterpret_cast<const float2*>(row + kt * 16 + 8 + 2 * t);

    float rx0 = lo.x - h16(lo.x), rx1 = lo.y - h16(lo.y);
    float rx2 = hi.x - h16(hi.x), rx3 = hi.y - h16(hi.y);
    float s  = lo.x * lo.x + lo.y * lo.y + hi.x * hi.x + hi.y * hi.y;
    float sb = rx0 * rx0 + rx1 * rx1 + rx2 * rx2 + rx3 * rx3;
#pragma unroll
    for (int off = 16; off > 0; off >>= 1) {
        s  += __shfl_xor_sync(0xFFFFFFFFu, s, off);
        sb += __shfl_xor_sync(0xFFFFFFFFu, sb, off);
    }
    if (lane == 0) {
        g_x2[r] = s; g_xb2[r] = sb;
        g_best1[r] = 0xFFFFFFFFu;
        g_best2[r] = 0xFFFFFFFFFFFFFFFFull;
    }
    if (warp == 0) {
        if (lane == 1) g_t1 = 0;
        if (lane == 2) g_t2 = 0;
        if (lane == 3) g_mc2e = 0;
        if (lane == 4) g_mcb2e = 0;
    }

    uint32_t w0 = packh(lo.x, lo.y);
    uint32_t w1 = packh(hi.x, hi.y);
    uint32_t* base = reinterpret_cast<uint32_t*>(&g_afrag[M][kt][(g & 7) * 4 + t]);
    if (g < 8) { base[0] = w0; base[2] = w1; }
    else       { base[1] = w0; base[3] = w1; }
}

// ---------------------------------------------------------------------------
// prep B: one warp per center -> c2, max-norm stats, a-plane B fragment
// ---------------------------------------------------------------------------
__global__ void prep_bc_kernel(const float* __restrict__ centers) {
    int warp = (blockIdx.x * blockDim.x + threadIdx.x) >> 5;
    int lane = threadIdx.x & 31;
    if (warp >= NCENT) return;
    int n = warp;
    int N = n >> 3, g = n & 7;
    int kt = lane >> 2, t = lane & 3;
    const float* row = centers + (size_t)n * DIM;
    float2 lo = *reinterpret_cast<const float2*>(row + kt * 16 + 2 * t);
    float2 hi = *reinterpret_cast<const float2*>(row + kt * 16 + 8 + 2 * t);

    float r0 = lo.x - h16(lo.x), r1 = lo.y - h16(lo.y);
    float r2 = hi.x - h16(hi.x), r3 = hi.y - h16(hi.y);
    float s  = lo.x * lo.x + lo.y * lo.y + hi.x * hi.x + hi.y * hi.y;
    float sb = r0 * r0 + r1 * r1 + r2 * r2 + r3 * r3;
#pragma unroll
    for (int off = 16; off > 0; off >>= 1) {
        s  += __shfl_xor_sync(0xFFFFFFFFu, s, off);
        sb += __shfl_xor_sync(0xFFFFFFFFu, sb, off);
    }
    if (lane == 0) {
        g_c2[n] = s;
        atomicMax(&g_mc2e,  encf(s));
        atomicMax(&g_mcb2e, encf(sb));
    }
    uint2 w;
    w.x = packh(lo.x, lo.y);
    w.y = packh(hi.x, hi.y);
    g_bfrag[N][kt][g * 4 + t] = w;
}

// ---------------------------------------------------------------------------
// single-plane GEMM chunk: NT n8-tiles, 2 m16-tiles; returns acc via callback
// ---------------------------------------------------------------------------
template<int NT>
__device__ __forceinline__ void gemm_chunk(float acc[2][NT][4], int mtb, int tile0, int l) {
    const uint4* __restrict__ Ap = &g_afrag[0][0][0] + (size_t)mtb * 256 + l;
    const uint2* __restrict__ Bp = &g_bfrag[0][0][0] + (size_t)tile0 * 256 + l;
#pragma unroll
    for (int mt = 0; mt < 2; mt++)
#pragma unroll
        for (int nt = 0; nt < NT; nt++)
#pragma unroll
            for (int q = 0; q < 4; q++) acc[mt][nt][q] = 0.0f;
#pragma unroll
    for (int kt = 0; kt < 8; kt++) {
        uint2 b2[NT];
#pragma unroll
        for (int nt = 0; nt < NT; nt++) b2[nt] = __ldg(Bp + (size_t)nt * 256 + kt * 32);
        uint4 a[2];
#pragma unroll
        for (int mt = 0; mt < 2; mt++) a[mt] = __ldg(Ap + (size_t)mt * 256 + kt * 32);
#pragma unroll
        for (int mt = 0; mt < 2; mt++)
#pragma unroll
            for (int nt = 0; nt < NT; nt++)
                mma16816(acc[mt][nt], a[mt], b2[nt].x, b2[nt].y);
    }
}

// ---------------------------------------------------------------------------
// sweep 1: approx (fp16 a-plane) distances, per-row min via u32 atomicMin
// ---------------------------------------------------------------------------
__global__ __launch_bounds__(128, 4)
void sweep1_kernel() {
    const int tid = threadIdx.x;
    const int w = tid >> 5, l = tid & 31;
    const int g = l >> 2, t = l & 3;
    const int mw = w >> 1, nw = w & 1;
    __shared__ int s_u;
    for (;;) {
        __syncthreads();
        if (tid == 0) s_u = atomicAdd(&g_t1, 1);
        __syncthreads();
        int u = s_u;
        if (u >= NUNITS) break;
        const int um = u & 511, s = u >> 9;
        const int r0 = um * 64;
        const int mtb = um * 4 + mw * 2;
        float x2r[4];
#pragma unroll
        for (int q = 0; q < 4; q++)
            x2r[q] = g_x2[r0 + mw * 32 + (q >> 1) * 16 + (q & 1) * 8 + g];
        float bv[4] = {INFINITY, INFINITY, INFINITY, INFINITY};
        const int tbase = s * NSLC_T;

#pragma unroll 1
        for (int ch = 0; ch < 7; ch++) {
            if (ch < 6) {
                float acc[2][8][4];
                int tile0 = tbase + ch * 16 + nw * 8;
                gemm_chunk<8>(acc, mtb, tile0, l);
#pragma unroll
                for (int nt = 0; nt < 8; nt++) {
                    int col0 = (tile0 + nt) * 8 + 2 * t;
                    float2 c2v = *reinterpret_cast<const float2*>(&g_c2[col0]);
#pragma unroll
                    for (int mt = 0; mt < 2; mt++) {
                        bv[mt*2+0] = fminf(bv[mt*2+0], (x2r[mt*2+0] + c2v.x) - 2.0f * acc[mt][nt][0]);
                        bv[mt*2+0] = fminf(bv[mt*2+0], (x2r[mt*2+0] + c2v.y) - 2.0f * acc[mt][nt][1]);
                        bv[mt*2+1] = fminf(bv[mt*2+1], (x2r[mt*2+1] + c2v.x) - 2.0f * acc[mt][nt][2]);
                        bv[mt*2+1] = fminf(bv[mt*2+1], (x2r[mt*2+1] + c2v.y) - 2.0f * acc[mt][nt][3]);
                    }
                }
            } else {
                float acc[2][2][4];
                int tile0 = tbase + 96 + nw * 2;
                gemm_chunk<2>(acc, mtb, tile0, l);
#pragma unroll
                for (int nt = 0; nt < 2; nt++) {
                    int col0 = (tile0 + nt) * 8 + 2 * t;
                    float2 c2v = *reinterpret_cast<const float2*>(&g_c2[col0]);
#pragma unroll
                    for (int mt = 0; mt < 2; mt++) {
                        bv[mt*2+0] = fminf(bv[mt*2+0], (x2r[mt*2+0] + c2v.x) - 2.0f * acc[mt][nt][0]);
                        bv[mt*2+0] = fminf(bv[mt*2+0], (x2r[mt*2+0] + c2v.y) - 2.0f * acc[mt][nt][1]);
                        bv[mt*2+1] = fminf(bv[mt*2+1], (x2r[mt*2+1] + c2v.x) - 2.0f * acc[mt][nt][2]);
                        bv[mt*2+1] = fminf(bv[mt*2+1], (x2r[mt*2+1] + c2v.y) - 2.0f * acc[mt][nt][3]);
                    }
                }
            }
        }
#pragma unroll
        for (int q = 0; q < 4; q++) {
#pragma unroll
            for (int off = 1; off <= 2; off <<= 1)
                bv[q] = fminf(bv[q], __shfl_xor_sync(0xFFFFFFFFu, bv[q], off));
        }
        if (t == 0) {
#pragma unroll
            for (int q = 0; q < 4; q++) {
                int row = r0 + mw * 32 + (q >> 1) * 16 + (q & 1) * 8 + g;
                atomicMin(&g_best1[row], encf(bv[q]));
            }
        }
    }
}

// ---------------------------------------------------------------------------
// exact refine for candidate hits (warp-cooperative, deterministic)
// ---------------------------------------------------------------------------
__device__ __noinline__ void process_hits(const float* __restrict__ x,
                                          const float* __restrict__ centers,
                                          unsigned f, int rbase, int cb, int lane) {
    unsigned mask = __ballot_sync(0xFFFFFFFFu, f != 0);
    while (mask) {
        int src = __ffs(mask) - 1;
        mask &= mask - 1;
        unsigned nib = __shfl_sync(0xFFFFFFFFu, f, src);
        int ts = src & 3, gs = src >> 2;
#pragma unroll
        for (int b = 0; b < 4; b++) {
            if ((nib >> b) & 1) {
                int r = rbase + ((b >> 1) & 1) * 8 + gs;
                int c = cb + 2 * ts + (b & 1);
                float4 xv = reinterpret_cast<const float4*>(x + (size_t)r * DIM)[lane];
                float4 cv = reinterpret_cast<const float4*>(centers + (size_t)c * DIM)[lane];
                float p = xv.x * cv.x;
                p = fmaf(xv.y, cv.y, p);
                p = fmaf(xv.z, cv.z, p);
                p = fmaf(xv.w, cv.w, p);
#pragma unroll
                for (int off = 16; off > 0; off >>= 1)
                    p += __shfl_xor_sync(0xFFFFFFFFu, p, off);
                float tt = g_x2[r] + g_c2[c];
                float sq = tt - 2.0f * p;
                if (lane == 0) {
                    unsigned long long key =
                        ((unsigned long long)encf(sq) << 32) | (unsigned long long)(uint32_t)c;
                    atomicMin(&g_best2[r], key);
                }
            }
        }
    }
}

// ---------------------------------------------------------------------------
// sweep 2: recompute approx, collect candidates <= threshold, exact-refine
// ---------------------------------------------------------------------------
template<int NT>
__device__ __forceinline__ void fold2(float acc[2][NT][4], int tile0, int rowbase0,
                                      const float* x2r, const float* th,
                                      const float* __restrict__ x,
                                      const float* __restrict__ centers,
                                      int l, int t) {
#pragma unroll
    for (int nt = 0; nt < NT; nt++) {
        int col0 = (tile0 + nt) * 8 + 2 * t;
        float2 c2v = *reinterpret_cast<const float2*>(&g_c2[col0]);
#pragma unroll
        for (int mt = 0; mt < 2; mt++) {
            float s00 = (x2r[mt*2+0] + c2v.x) - 2.0f * acc[mt][nt][0];
            float s01 = (x2r[mt*2+0] + c2v.y) - 2.0f * acc[mt][nt][1];
            float s10 = (x2r[mt*2+1] + c2v.x) - 2.0f * acc[mt][nt][2];
            float s11 = (x2r[mt*2+1] + c2v.y) - 2.0f * acc[mt][nt][3];
            unsigned f = (s00 <= th[mt*2+0] ? 1u : 0u)
                       | (s01 <= th[mt*2+0] ? 2u : 0u)
                       | (s10 <= th[mt*2+1] ? 4u : 0u)
                       | (s11 <= th[mt*2+1] ? 8u : 0u);
            if (__any_sync(0xFFFFFFFFu, f != 0))
                process_hits(x, centers, f, rowbase0 + mt * 16, (tile0 + nt) * 8, l & 31);
        }
    }
}

__global__ __launch_bounds__(128, 4)
void sweep2_kernel(const float* __restrict__ x, const float* __restrict__ centers) {
    const int tid = threadIdx.x;
    const int w = tid >> 5, l = tid & 31;
    const int g = l >> 2, t = l & 3;
    const int mw = w >> 1, nw = w & 1;
    const float cn  = sqrtf(decf(g_mc2e));
    const float cbn = sqrtf(decf(g_mcb2e));
    __shared__ int s_u;
    for (;;) {
        __syncthreads();
        if (tid == 0) s_u = atomicAdd(&g_t2, 1);
        __syncthreads();
        int u = s_u;
        if (u >= NUNITS) break;
        const int um = u & 511, s = u >> 9;
        const int r0 = um * 64;
        const int mtb = um * 4 + mw * 2;
        const int rowbase0 = r0 + mw * 32;
        float x2r[4], th[4];
#pragma unroll
        for (int q = 0; q < 4; q++) {
            int row = rowbase0 + (q >> 1) * 16 + (q & 1) * 8 + g;
            float x2 = g_x2[row];
            float xn = sqrtf(x2), xbn = sqrtf(g_xb2[row]);
            float E = xbn * cn + xn * cbn + xbn * cbn + 2e-6f * xn * cn;
            x2r[q] = x2;
            th[q] = decf(g_best1[row]) + 4.0f * E + 4e-3f;
        }
        const int tbase = s * NSLC_T;
#pragma unroll 1
        for (int ch = 0; ch < 7; ch++) {
            if (ch < 6) {
                float acc[2][8][4];
                int tile0 = tbase + ch * 16 + nw * 8;
                gemm_chunk<8>(acc, mtb, tile0, l);
                fold2<8>(acc, tile0, rowbase0, x2r, th, x, centers, l, t);
            } else {
                float acc[2][2][4];
                int tile0 = tbase + 96 + nw * 2;
                gemm_chunk<2>(acc, mtb, tile0, l);
                fold2<2>(acc, tile0, rowbase0, x2r, th, x, centers, l, t);
            }
        }
    }
}

// ---------------------------------------------------------------------------
// final: decode exact best key, write scalars + gather quantized row
// ---------------------------------------------------------------------------
__global__ void final_kernel(const float* __restrict__ centers, float* __restrict__ out) {
    int warp = (blockIdx.x * blockDim.x + threadIdx.x) >> 5;
    int lane = threadIdx.x & 31;
    if (warp >= BATCH) return;
    unsigned long long key = g_best2[warp];
    int fi = (int)(uint32_t)(key & 0xFFFFFFFFull);
    float sq = decf((uint32_t)(key >> 32));
    if (lane == 0) {
        float* outAssign = out + (size_t)BATCH * DIM;
        float* outDist   = outAssign + BATCH;
        float* outClass  = outDist + BATCH;
        outAssign[warp] = (float)(fi % KC);
        outDist[warp]   = sqrtf(fmaxf(sq, 0.0f));
        outClass[warp]  = (float)(fi / KC);
    }
    float4 v = reinterpret_cast<const float4*>(centers)[(size_t)fi * 32 + lane];
    reinterpret_cast<float4*>(out)[(size_t)warp * 32 + lane] = v;
}

extern "C" void kernel_launch(void* const* d_in, const int* in_sizes, int n_in,
                              void* d_out, int out_size) {
    const float* x       = (const float*)d_in[0];
    const float* centers = (const float*)d_in[1];
    float* out = (float*)d_out;

    prep_ax_kernel<<<(BATCH * 32 + 255) / 256, 256>>>(x);
    prep_bc_kernel<<<(NCENT * 32 + 255) / 256, 256>>>(centers);
    sweep1_kernel<<<GRID_SW, 128>>>();
    sweep2_kernel<<<GRID_SW, 128>>>(x, centers);
    final_kernel<<<(BATCH * 32 + 255) / 256, 256>>>(centers, out);
}

// round 9
// speedup vs baseline: 1.9178x; 1.9178x over previous
#include <cuda_runtime.h>
#include <cuda_fp16.h>
#include <math.h>
#include <stdint.h>

// ---------------- problem constants ----------------
#define BATCH     32768
#define DIM       128
#define NCENT     6400
#define KC        64
#define AMT       (BATCH / 16)     // 2048 A row-tiles (m16)
#define BNT       (NCENT / 8)      // 800  B col-tiles (n8)
#define NSLICES   10
#define NSLC_T    80               // n8-tiles per slice (640 centers)
#define NUNITS    (512 * NSLICES)  // 5120
#define NGRP      100              // 64-center groups
#define GRID_SW   444              // 148 SMs x occ 3

// ---------------- device scratch ----------------
__device__ uint4 g_afrag[AMT][8][32];      // 8.4 MB (fp16 main plane, A frag)
__device__ uint4 g_bfrag[BNT][4][32];      // 1.6 MB (fp16 main plane, B frag, kt-pair)
__device__ float g_c2[NCENT];
__device__ float g_x2[BATCH];
__device__ float g_xb2[BATCH];             // ||x - fp16(x)||^2
__device__ float g_smin[NGRP][BATCH];      // per (64-center group, row): min(c2 - 2*dotApprox)
__device__ int   g_t1;
__device__ unsigned g_mc2e, g_mcb2e;       // enc(max c2), enc(max ||c_res||^2)

// ---------------- helpers ----------------
__device__ __forceinline__ uint32_t packh(float lo, float hi) {
    __half2 h = __floats2half2_rn(lo, hi);
    return *reinterpret_cast<uint32_t*>(&h);
}
__device__ __forceinline__ float h16(float v) { return __half2float(__float2half_rn(v)); }
__device__ __forceinline__ uint32_t encf(float f) {
    uint32_t u = __float_as_uint(f);
    return (u & 0x80000000u) ? ~u : (u | 0x80000000u);
}
__device__ __forceinline__ float decf(uint32_t e) {
    uint32_t u = (e & 0x80000000u) ? (e ^ 0x80000000u) : ~e;
    return __uint_as_float(u);
}
__device__ __forceinline__ void mma16816(float* d, const uint4& a,
                                         uint32_t b0, uint32_t b1) {
    asm volatile(
        "mma.sync.aligned.m16n8k16.row.col.f32.f16.f16.f32 "
        "{%0,%1,%2,%3}, {%4,%5,%6,%7}, {%8,%9}, {%0,%1,%2,%3};"
        : "+f"(d[0]), "+f"(d[1]), "+f"(d[2]), "+f"(d[3])
        : "r"(a.x), "r"(a.y), "r"(a.z), "r"(a.w), "r"(b0), "r"(b1));
}

// ---------------------------------------------------------------------------
// prep A: one warp per x row -> x2, xb2, A fragment; global resets
// ---------------------------------------------------------------------------
__global__ void prep_ax_kernel(const float* __restrict__ x) {
    int warp = (blockIdx.x * blockDim.x + threadIdx.x) >> 5;
    int lane = threadIdx.x & 31;
    if (warp >= BATCH) return;
    int r = warp;
    int M = r >> 4, g = r & 15;
    int kt = lane >> 2, t = lane & 3;
    const float* row = x + (size_t)r * DIM;
    float2 lo = *reinterpret_cast<const float2*>(row + kt * 16 + 2 * t);
    float2 hi = *reinterpret_cast<const float2*>(row + kt * 16 + 8 + 2 * t);

    float r0 = lo.x - h16(lo.x), r1 = lo.y - h16(lo.y);
    float r2 = hi.x - h16(hi.x), r3 = hi.y - h16(hi.y);
    float s  = lo.x * lo.x + lo.y * lo.y + hi.x * hi.x + hi.y * hi.y;
    float sb = r0 * r0 + r1 * r1 + r2 * r2 + r3 * r3;
#pragma unroll
    for (int off = 16; off > 0; off >>= 1) {
        s  += __shfl_xor_sync(0xFFFFFFFFu, s, off);
        sb += __shfl_xor_sync(0xFFFFFFFFu, sb, off);
    }
    if (lane == 0) { g_x2[r] = s; g_xb2[r] = sb; }
    if (warp == 0) {
        if (lane == 1) g_t1 = 0;
        if (lane == 2) g_mc2e = 0;
        if (lane == 3) g_mcb2e = 0;
    }
    uint32_t w0 = packh(lo.x, lo.y);
    uint32_t w1 = packh(hi.x, hi.y);
    uint32_t* base = reinterpret_cast<uint32_t*>(&g_afrag[M][kt][(g & 7) * 4 + t]);
    if (g < 8) { base[0] = w0; base[2] = w1; }
    else       { base[1] = w0; base[3] = w1; }
}

// ---------------------------------------------------------------------------
// prep B: one warp per center -> c2, norm maxima, B fragment (kt-pair packed)
// ---------------------------------------------------------------------------
__global__ void prep_bc_kernel(const float* __restrict__ centers) {
    int warp = (blockIdx.x * blockDim.x + threadIdx.x) >> 5;
    int lane = threadIdx.x & 31;
    if (warp >= NCENT) return;
    int n = warp;
    int N = n >> 3, g = n & 7;
    int j = lane & 15;
    int kt2 = j >> 2, t = j & 3;
    const float* row = centers + (size_t)n * DIM;
    int c0 = kt2 * 32 + 2 * t;
    float2 e0, e1, o0, o1;
    float s = 0.0f, sb = 0.0f;
    if (lane < 16) {
        e0 = *reinterpret_cast<const float2*>(row + c0);
        e1 = *reinterpret_cast<const float2*>(row + c0 + 8);
        o0 = *reinterpret_cast<const float2*>(row + c0 + 16);
        o1 = *reinterpret_cast<const float2*>(row + c0 + 24);
        float q0 = e0.x - h16(e0.x), q1 = e0.y - h16(e0.y);
        float q2 = e1.x - h16(e1.x), q3 = e1.y - h16(e1.y);
        float q4 = o0.x - h16(o0.x), q5 = o0.y - h16(o0.y);
        float q6 = o1.x - h16(o1.x), q7 = o1.y - h16(o1.y);
        s  = e0.x*e0.x + e0.y*e0.y + e1.x*e1.x + e1.y*e1.y
           + o0.x*o0.x + o0.y*o0.y + o1.x*o1.x + o1.y*o1.y;
        sb = q0*q0 + q1*q1 + q2*q2 + q3*q3 + q4*q4 + q5*q5 + q6*q6 + q7*q7;
    }
#pragma unroll
    for (int off = 16; off > 0; off >>= 1) {
        s  += __shfl_xor_sync(0xFFFFFFFFu, s, off);
        sb += __shfl_xor_sync(0xFFFFFFFFu, sb, off);
    }
    if (lane == 0) {
        g_c2[n] = s;
        atomicMax(&g_mc2e,  encf(s));
        atomicMax(&g_mcb2e, encf(sb));
    }
    if (lane < 16) {
        uint4 w;
        w.x = packh(e0.x, e0.y);
        w.y = packh(e1.x, e1.y);
        w.z = packh(o0.x, o0.y);
        w.w = packh(o1.x, o1.y);
        g_bfrag[N][kt2][g * 4 + t] = w;
    }
}

// ---------------------------------------------------------------------------
// sweep 1: single-plane fp16 GEMM; per (row, 64-center group) min(c2 - 2*dot)
// persistent occ-3 CTAs pull (64-row x 640-center) units.
// ---------------------------------------------------------------------------
__global__ __launch_bounds__(128, 3)
void sweep1_kernel() {
    const int tid = threadIdx.x;
    const int w = tid >> 5, l = tid & 31;
    const int g = l >> 2, t = l & 3;
    const int mw = w >> 1, nw = w & 1;
    const uint4* __restrict__ Abase = &g_afrag[0][0][0];
    const uint4* __restrict__ Bbase = &g_bfrag[0][0][0];
    __shared__ int s_u;
    for (;;) {
        __syncthreads();
        if (tid == 0) s_u = atomicAdd(&g_t1, 1);
        __syncthreads();
        int u = s_u;
        if (u >= NUNITS) break;
        const int um = u & 511, s = u >> 9;
        const int r0 = um * 64;
        const int mtb = um * 4 + mw * 2;
        const int tbase = s * NSLC_T;

#pragma unroll 1
        for (int ch = 0; ch < 5; ch++) {
            const int tile0 = tbase + ch * 16 + nw * 8;
            float acc[2][8][4];
#pragma unroll
            for (int mt = 0; mt < 2; mt++)
#pragma unroll
                for (int nt = 0; nt < 8; nt++)
#pragma unroll
                    for (int q = 0; q < 4; q++) acc[mt][nt][q] = 0.0f;

            const uint4* Ap = Abase + (size_t)mtb * 256 + l;
            const uint4* Bp = Bbase + (size_t)tile0 * 128 + l;
#pragma unroll
            for (int kt2 = 0; kt2 < 4; kt2++) {
                uint4 b4[8];
#pragma unroll
                for (int nt = 0; nt < 8; nt++) b4[nt] = __ldg(Bp + (size_t)nt * 128 + kt2 * 32);
                uint4 a0[2], a1[2];
#pragma unroll
                for (int mt = 0; mt < 2; mt++) a0[mt] = __ldg(Ap + (size_t)mt * 256 + (2 * kt2) * 32);
#pragma unroll
                for (int mt = 0; mt < 2; mt++) a1[mt] = __ldg(Ap + (size_t)mt * 256 + (2 * kt2 + 1) * 32);
#pragma unroll
                for (int mt = 0; mt < 2; mt++)
#pragma unroll
                    for (int nt = 0; nt < 8; nt++)
                        mma16816(acc[mt][nt], a0[mt], b4[nt].x, b4[nt].y);
#pragma unroll
                for (int mt = 0; mt < 2; mt++)
#pragma unroll
                    for (int nt = 0; nt < 8; nt++)
                        mma16816(acc[mt][nt], a1[mt], b4[nt].z, b4[nt].w);
            }

            // fold: per-row min of (c2 - 2*dot) over this warp's 64 centers
            float bv[4] = {INFINITY, INFINITY, INFINITY, INFINITY};
#pragma unroll
            for (int nt = 0; nt < 8; nt++) {
                int col0 = (tile0 + nt) * 8 + 2 * t;
                float2 c2v = *reinterpret_cast<const float2*>(&g_c2[col0]);
#pragma unroll
                for (int mt = 0; mt < 2; mt++) {
                    bv[mt*2+0] = fminf(bv[mt*2+0], c2v.x - 2.0f * acc[mt][nt][0]);
                    bv[mt*2+0] = fminf(bv[mt*2+0], c2v.y - 2.0f * acc[mt][nt][1]);
                    bv[mt*2+1] = fminf(bv[mt*2+1], c2v.x - 2.0f * acc[mt][nt][2]);
                    bv[mt*2+1] = fminf(bv[mt*2+1], c2v.y - 2.0f * acc[mt][nt][3]);
                }
            }
#pragma unroll
            for (int q = 0; q < 4; q++) {
#pragma unroll
                for (int off = 1; off <= 2; off <<= 1)
                    bv[q] = fminf(bv[q], __shfl_xor_sync(0xFFFFFFFFu, bv[q], off));
            }
            if (t == 0) {
                int grp = s * 10 + ch * 2 + nw;
#pragma unroll
                for (int q = 0; q < 4; q++) {
                    int row = r0 + mw * 32 + (q >> 1) * 16 + (q & 1) * 8 + g;
                    g_smin[grp][row] = bv[q];
                }
            }
        }
    }
}

// ---------------------------------------------------------------------------
// phase 2: per-row threshold + exact fp32 rescan of flagged groups + outputs
// one warp per row; block = 8 rows (256 threads)
// ---------------------------------------------------------------------------
__global__ __launch_bounds__(256)
void phase2_kernel(const float* __restrict__ x, const float* __restrict__ centers,
                   float* __restrict__ out) {
    __shared__ float sm[8][NGRP];
    const int tid = threadIdx.x;
    const int w = tid >> 5, l = tid & 31;
    const int rowbase = blockIdx.x * 8;

    // cooperative coalesced load of the 8 rows' group minima
    for (int i = tid; i < 8 * NGRP; i += 256) {
        int grp = i >> 3, r8 = i & 7;
        sm[r8][grp] = g_smin[grp][rowbase + r8];
    }
    __syncthreads();

    const int row = rowbase + w;
    const float x2 = g_x2[row];
    const float xn = sqrtf(x2), xbn = sqrtf(g_xb2[row]);
    const float cn = sqrtf(decf(g_mc2e)), cbn = sqrtf(decf(g_mcb2e));
    const float E = xbn * cn + xn * cbn + xbn * cbn + 2e-6f * xn * cn;

    float v0 = sm[w][l], v1 = sm[w][l + 32], v2 = sm[w][l + 64];
    float v3 = (l < 4) ? sm[w][96 + l] : INFINITY;
    float m = fminf(fminf(v0, v1), fminf(v2, v3));
#pragma unroll
    for (int off = 16; off > 0; off >>= 1)
        m = fminf(m, __shfl_xor_sync(0xFFFFFFFFu, m, off));
    const float th = m + 4.0f * E + 4e-3f;

    unsigned segs[4];
    segs[0] = __ballot_sync(0xFFFFFFFFu, v0 <= th);
    segs[1] = __ballot_sync(0xFFFFFFFFu, v1 <= th);
    segs[2] = __ballot_sync(0xFFFFFFFFu, v2 <= th);
    segs[3] = __ballot_sync(0xFFFFFFFFu, (l < 4) && (v3 <= th));

    const float4 xv = reinterpret_cast<const float4*>(x + (size_t)row * DIM)[l];
    float bestv = INFINITY;
    int   besti = 0;
#pragma unroll 1
    for (int seg = 0; seg < 4; seg++) {
        unsigned mm = segs[seg];
        while (mm) {
            int grp = seg * 32 + __ffs(mm) - 1;
            mm &= mm - 1;
            int cbase = grp * 64;
#pragma unroll 4
            for (int c = cbase; c < cbase + 64; c++) {
                float4 cv = reinterpret_cast<const float4*>(centers)[(size_t)c * 32 + l];
                float p = xv.x * cv.x;
                p = fmaf(xv.y, cv.y, p);
                p = fmaf(xv.z, cv.z, p);
                p = fmaf(xv.w, cv.w, p);
#pragma unroll
                for (int off = 16; off > 0; off >>= 1)
                    p += __shfl_xor_sync(0xFFFFFFFFu, p, off);
                float sq = (x2 + g_c2[c]) - 2.0f * p;
                if (sq < bestv) { bestv = sq; besti = c; }
            }
        }
    }

    if (l == 0) {
        float* outAssign = out + (size_t)BATCH * DIM;
        float* outDist   = outAssign + BATCH;
        float* outClass  = outDist + BATCH;
        outAssign[row] = (float)(besti % KC);
        outDist[row]   = sqrtf(fmaxf(bestv, 0.0f));
        outClass[row]  = (float)(besti / KC);
    }
    float4 cb = reinterpret_cast<const float4*>(centers)[(size_t)besti * 32 + l];
    reinterpret_cast<float4*>(out)[(size_t)row * 32 + l] = cb;
}

extern "C" void kernel_launch(void* const* d_in, const int* in_sizes, int n_in,
                              void* d_out, int out_size) {
    const float* x       = (const float*)d_in[0];
    const float* centers = (const float*)d_in[1];
    float* out = (float*)d_out;

    prep_ax_kernel<<<(BATCH * 32 + 255) / 256, 256>>>(x);
    prep_bc_kernel<<<(NCENT * 32 + 255) / 256, 256>>>(centers);
    sweep1_kernel<<<GRID_SW, 128>>>();
    phase2_kernel<<<BATCH / 8, 256>>>(x, centers, out);
}

// round 10
// speedup vs baseline: 2.7485x; 1.4332x over previous
#include <cuda_runtime.h>
#include <cuda_fp16.h>
#include <math.h>
#include <stdint.h>

// ---------------- problem constants ----------------
#define BATCH     32768
#define DIM       128
#define NCENT     6400
#define KC        64
#define AMT       (BATCH / 16)     // 2048 A row-tiles (m16)
#define BNT       (NCENT / 8)      // 800  B col-tiles (n8)
#define NSLICES   10
#define NSLC_T    80               // n8-tiles per slice (640 centers)
#define NUNITS    (512 * NSLICES)  // 5120
#define NGRP      400              // 16-center groups
#define GRID_SW   444              // 148 SMs x occ 3

// ---------------- device scratch ----------------
__device__ uint4 g_afrag[AMT][8][32];      // 8.4 MB (fp16 main plane, A frag)
__device__ uint4 g_bfrag[BNT][4][32];      // 1.6 MB (fp16 main plane, B frag, kt-pair)
__device__ float g_c2[NCENT];
__device__ float g_x2[BATCH];
__device__ float g_xb2[BATCH];             // ||x - fp16(x)||^2
__device__ float g_smin[BATCH][NGRP];      // per (row, 16-center group): min(c2 - 2*dotApprox)
__device__ int   g_t1;
__device__ unsigned g_mc2e, g_mcb2e;       // enc(max c2), enc(max ||c_res||^2)

// ---------------- helpers ----------------
__device__ __forceinline__ uint32_t packh(float lo, float hi) {
    __half2 h = __floats2half2_rn(lo, hi);
    return *reinterpret_cast<uint32_t*>(&h);
}
__device__ __forceinline__ float h16(float v) { return __half2float(__float2half_rn(v)); }
__device__ __forceinline__ uint32_t encf(float f) {
    uint32_t u = __float_as_uint(f);
    return (u & 0x80000000u) ? ~u : (u | 0x80000000u);
}
__device__ __forceinline__ float decf(uint32_t e) {
    uint32_t u = (e & 0x80000000u) ? (e ^ 0x80000000u) : ~e;
    return __uint_as_float(u);
}
__device__ __forceinline__ void mma16816(float* d, const uint4& a,
                                         uint32_t b0, uint32_t b1) {
    asm volatile(
        "mma.sync.aligned.m16n8k16.row.col.f32.f16.f16.f32 "
        "{%0,%1,%2,%3}, {%4,%5,%6,%7}, {%8,%9}, {%0,%1,%2,%3};"
        : "+f"(d[0]), "+f"(d[1]), "+f"(d[2]), "+f"(d[3])
        : "r"(a.x), "r"(a.y), "r"(a.z), "r"(a.w), "r"(b0), "r"(b1));
}

// ---------------------------------------------------------------------------
// prep A: one warp per x row -> x2, xb2, A fragment; global resets
// ---------------------------------------------------------------------------
__global__ void prep_ax_kernel(const float* __restrict__ x) {
    int warp = (blockIdx.x * blockDim.x + threadIdx.x) >> 5;
    int lane = threadIdx.x & 31;
    if (warp >= BATCH) return;
    int r = warp;
    int M = r >> 4, g = r & 15;
    int kt = lane >> 2, t = lane & 3;
    const float* row = x + (size_t)r * DIM;
    float2 lo = *reinterpret_cast<const float2*>(row + kt * 16 + 2 * t);
    float2 hi = *reinterpret_cast<const float2*>(row + kt * 16 + 8 + 2 * t);

    float r0 = lo.x - h16(lo.x), r1 = lo.y - h16(lo.y);
    float r2 = hi.x - h16(hi.x), r3 = hi.y - h16(hi.y);
    float s  = lo.x * lo.x + lo.y * lo.y + hi.x * hi.x + hi.y * hi.y;
    float sb = r0 * r0 + r1 * r1 + r2 * r2 + r3 * r3;
#pragma unroll
    for (int off = 16; off > 0; off >>= 1) {
        s  += __shfl_xor_sync(0xFFFFFFFFu, s, off);
        sb += __shfl_xor_sync(0xFFFFFFFFu, sb, off);
    }
    if (lane == 0) { g_x2[r] = s; g_xb2[r] = sb; }
    if (warp == 0) {
        if (lane == 1) g_t1 = 0;
        if (lane == 2) g_mc2e = 0;
        if (lane == 3) g_mcb2e = 0;
    }
    uint32_t w0 = packh(lo.x, lo.y);
    uint32_t w1 = packh(hi.x, hi.y);
    uint32_t* base = reinterpret_cast<uint32_t*>(&g_afrag[M][kt][(g & 7) * 4 + t]);
    if (g < 8) { base[0] = w0; base[2] = w1; }
    else       { base[1] = w0; base[3] = w1; }
}

// ---------------------------------------------------------------------------
// prep B: one warp per center -> c2, norm maxima, B fragment (kt-pair packed)
// ---------------------------------------------------------------------------
__global__ void prep_bc_kernel(const float* __restrict__ centers) {
    int warp = (blockIdx.x * blockDim.x + threadIdx.x) >> 5;
    int lane = threadIdx.x & 31;
    if (warp >= NCENT) return;
    int n = warp;
    int N = n >> 3, g = n & 7;
    int j = lane & 15;
    int kt2 = j >> 2, t = j & 3;
    const float* row = centers + (size_t)n * DIM;
    int c0 = kt2 * 32 + 2 * t;
    float2 e0, e1, o0, o1;
    float s = 0.0f, sb = 0.0f;
    if (lane < 16) {
        e0 = *reinterpret_cast<const float2*>(row + c0);
        e1 = *reinterpret_cast<const float2*>(row + c0 + 8);
        o0 = *reinterpret_cast<const float2*>(row + c0 + 16);
        o1 = *reinterpret_cast<const float2*>(row + c0 + 24);
        float q0 = e0.x - h16(e0.x), q1 = e0.y - h16(e0.y);
        float q2 = e1.x - h16(e1.x), q3 = e1.y - h16(e1.y);
        float q4 = o0.x - h16(o0.x), q5 = o0.y - h16(o0.y);
        float q6 = o1.x - h16(o1.x), q7 = o1.y - h16(o1.y);
        s  = e0.x*e0.x + e0.y*e0.y + e1.x*e1.x + e1.y*e1.y
           + o0.x*o0.x + o0.y*o0.y + o1.x*o1.x + o1.y*o1.y;
        sb = q0*q0 + q1*q1 + q2*q2 + q3*q3 + q4*q4 + q5*q5 + q6*q6 + q7*q7;
    }
#pragma unroll
    for (int off = 16; off > 0; off >>= 1) {
        s  += __shfl_xor_sync(0xFFFFFFFFu, s, off);
        sb += __shfl_xor_sync(0xFFFFFFFFu, sb, off);
    }
    if (lane == 0) {
        g_c2[n] = s;
        atomicMax(&g_mc2e,  encf(s));
        atomicMax(&g_mcb2e, encf(sb));
    }
    if (lane < 16) {
        uint4 w;
        w.x = packh(e0.x, e0.y);
        w.y = packh(e1.x, e1.y);
        w.z = packh(o0.x, o0.y);
        w.w = packh(o1.x, o1.y);
        g_bfrag[N][kt2][g * 4 + t] = w;
    }
}

// ---------------------------------------------------------------------------
// sweep 1: single-plane fp16 GEMM; per (row, 16-center group) min(c2 - 2*dot)
// persistent occ-3 CTAs pull (64-row x 640-center) units.
// ---------------------------------------------------------------------------
__global__ __launch_bounds__(128, 3)
void sweep1_kernel() {
    const int tid = threadIdx.x;
    const int w = tid >> 5, l = tid & 31;
    const int g = l >> 2, t = l & 3;
    const int mw = w >> 1, nw = w & 1;
    const uint4* __restrict__ Abase = &g_afrag[0][0][0];
    const uint4* __restrict__ Bbase = &g_bfrag[0][0][0];
    __shared__ int s_u;
    for (;;) {
        __syncthreads();
        if (tid == 0) s_u = atomicAdd(&g_t1, 1);
        __syncthreads();
        int u = s_u;
        if (u >= NUNITS) break;
        const int um = u & 511, s = u >> 9;
        const int r0 = um * 64;
        const int mtb = um * 4 + mw * 2;
        const int tbase = s * NSLC_T;

#pragma unroll 1
        for (int ch = 0; ch < 5; ch++) {
            const int tile0 = tbase + ch * 16 + nw * 8;
            float acc[2][8][4];
#pragma unroll
            for (int mt = 0; mt < 2; mt++)
#pragma unroll
                for (int nt = 0; nt < 8; nt++)
#pragma unroll
                    for (int q = 0; q < 4; q++) acc[mt][nt][q] = 0.0f;

            const uint4* Ap = Abase + (size_t)mtb * 256 + l;
            const uint4* Bp = Bbase + (size_t)tile0 * 128 + l;
#pragma unroll
            for (int kt2 = 0; kt2 < 4; kt2++) {
                uint4 b4[8];
#pragma unroll
                for (int nt = 0; nt < 8; nt++) b4[nt] = __ldg(Bp + (size_t)nt * 128 + kt2 * 32);
                uint4 a0[2], a1[2];
#pragma unroll
                for (int mt = 0; mt < 2; mt++) a0[mt] = __ldg(Ap + (size_t)mt * 256 + (2 * kt2) * 32);
#pragma unroll
                for (int mt = 0; mt < 2; mt++) a1[mt] = __ldg(Ap + (size_t)mt * 256 + (2 * kt2 + 1) * 32);
#pragma unroll
                for (int mt = 0; mt < 2; mt++)
#pragma unroll
                    for (int nt = 0; nt < 8; nt++)
                        mma16816(acc[mt][nt], a0[mt], b4[nt].x, b4[nt].y);
#pragma unroll
                for (int mt = 0; mt < 2; mt++)
#pragma unroll
                    for (int nt = 0; nt < 8; nt++)
                        mma16816(acc[mt][nt], a1[mt], b4[nt].z, b4[nt].w);
            }

            // fold: per-row min of (c2 - 2*dot) per 16-center group (nt pairs)
            float bv[4][4];   // [row slot][group within chunk]
#pragma unroll
            for (int sl = 0; sl < 4; sl++)
#pragma unroll
                for (int gi = 0; gi < 4; gi++) bv[sl][gi] = INFINITY;
#pragma unroll
            for (int nt = 0; nt < 8; nt++) {
                int gi = nt >> 1;
                int col0 = (tile0 + nt) * 8 + 2 * t;
                float2 c2v = *reinterpret_cast<const float2*>(&g_c2[col0]);
#pragma unroll
                for (int mt = 0; mt < 2; mt++) {
                    float m0 = fminf(c2v.x - 2.0f * acc[mt][nt][0], c2v.y - 2.0f * acc[mt][nt][1]);
                    float m1 = fminf(c2v.x - 2.0f * acc[mt][nt][2], c2v.y - 2.0f * acc[mt][nt][3]);
                    bv[mt*2+0][gi] = fminf(bv[mt*2+0][gi], m0);
                    bv[mt*2+1][gi] = fminf(bv[mt*2+1][gi], m1);
                }
            }
#pragma unroll
            for (int sl = 0; sl < 4; sl++)
#pragma unroll
                for (int gi = 0; gi < 4; gi++) {
                    bv[sl][gi] = fminf(bv[sl][gi], __shfl_xor_sync(0xFFFFFFFFu, bv[sl][gi], 1));
                    bv[sl][gi] = fminf(bv[sl][gi], __shfl_xor_sync(0xFFFFFFFFu, bv[sl][gi], 2));
                }
            if (t == 0) {
                int grpbase = tile0 >> 1;      // multiple of 4
#pragma unroll
                for (int sl = 0; sl < 4; sl++) {
                    int row = r0 + mw * 32 + (sl >> 1) * 16 + (sl & 1) * 8 + g;
                    float4 v = make_float4(bv[sl][0], bv[sl][1], bv[sl][2], bv[sl][3]);
                    *reinterpret_cast<float4*>(&g_smin[row][grpbase]) = v;
                }
            }
        }
    }
}

// ---------------------------------------------------------------------------
// phase 2: per-row threshold + exact fp32 rescan of flagged 16-groups + outputs
// one warp per row; block = 8 rows
// ---------------------------------------------------------------------------
__global__ __launch_bounds__(256)
void phase2_kernel(const float* __restrict__ x, const float* __restrict__ centers,
                   float* __restrict__ out) {
    const int tid = threadIdx.x;
    const int w = tid >> 5, l = tid & 31;
    const int row = blockIdx.x * 8 + w;

    const float4* rm4 = reinterpret_cast<const float4*>(&g_smin[row][0]);  // 100 float4
    float4 v[4];
    v[0] = rm4[l];
    v[1] = rm4[l + 32];
    v[2] = rm4[l + 64];
    v[3] = (l < 4) ? rm4[l + 96] : make_float4(INFINITY, INFINITY, INFINITY, INFINITY);

    float m = INFINITY;
#pragma unroll
    for (int k = 0; k < 4; k++)
        m = fminf(m, fminf(fminf(v[k].x, v[k].y), fminf(v[k].z, v[k].w)));
#pragma unroll
    for (int off = 16; off > 0; off >>= 1)
        m = fminf(m, __shfl_xor_sync(0xFFFFFFFFu, m, off));

    const float x2 = g_x2[row];
    const float xn = sqrtf(x2), xbn = sqrtf(g_xb2[row]);
    const float cn = sqrtf(decf(g_mc2e)), cbn = sqrtf(decf(g_mcb2e));
    const float E = xbn * cn + xn * cbn + xbn * cbn + 2e-6f * xn * cn;
    const float th = m + 4.0f * E + 4e-3f;

    // per-lane 16-bit flags: nibble k = float4 k, bit j = component j
    unsigned f = 0;
#pragma unroll
    for (int k = 0; k < 4; k++) {
        unsigned nib = (v[k].x <= th ? 1u : 0u) | (v[k].y <= th ? 2u : 0u)
                     | (v[k].z <= th ? 4u : 0u) | (v[k].w <= th ? 8u : 0u);
        f |= nib << (4 * k);
    }

    const float4 xv = reinterpret_cast<const float4*>(x + (size_t)row * DIM)[l];
    float bestv = INFINITY;
    int   besti = 0;

    unsigned mask = __ballot_sync(0xFFFFFFFFu, f != 0);
    while (mask) {
        int src = __ffs(mask) - 1;
        mask &= mask - 1;
        unsigned fs = __shfl_sync(0xFFFFFFFFu, f, src);
        while (fs) {
            int b = __ffs(fs) - 1;
            fs &= fs - 1;
            int k = b >> 2, j = b & 3;
            int grp = (src + 32 * k) * 4 + j;
            int cbase = grp * 16;
#pragma unroll 4
            for (int c = cbase; c < cbase + 16; c++) {
                float4 cv = reinterpret_cast<const float4*>(centers)[(size_t)c * 32 + l];
                float p = xv.x * cv.x;
                p = fmaf(xv.y, cv.y, p);
                p = fmaf(xv.z, cv.z, p);
                p = fmaf(xv.w, cv.w, p);
#pragma unroll
                for (int off = 16; off > 0; off >>= 1)
                    p += __shfl_xor_sync(0xFFFFFFFFu, p, off);
                float sq = (x2 + g_c2[c]) - 2.0f * p;
                // order-independent: strict-min with first-index tie-break
                if (sq < bestv || (sq == bestv && c < besti)) { bestv = sq; besti = c; }
            }
        }
    }

    if (l == 0) {
        float* outAssign = out + (size_t)BATCH * DIM;
        float* outDist   = outAssign + BATCH;
        float* outClass  = outDist + BATCH;
        outAssign[row] = (float)(besti % KC);
        outDist[row]   = sqrtf(fmaxf(bestv, 0.0f));
        outClass[row]  = (float)(besti / KC);
    }
    float4 cb = reinterpret_cast<const float4*>(centers)[(size_t)besti * 32 + l];
    reinterpret_cast<float4*>(out)[(size_t)row * 32 + l] = cb;
}

extern "C" void kernel_launch(void* const* d_in, const int* in_sizes, int n_in,
                              void* d_out, int out_size) {
    const float* x       = (const float*)d_in[0];
    const float* centers = (const float*)d_in[1];
    float* out = (float*)d_out;

    prep_ax_kernel<<<(BATCH * 32 + 255) / 256, 256>>>(x);
    prep_bc_kernel<<<(NCENT * 32 + 255) / 256, 256>>>(centers);
    sweep1_kernel<<<GRID_SW, 128>>>();
    phase2_kernel<<<BATCH / 8, 256>>>(x, centers, out);
}